// round 6
// baseline (speedup 1.0000x reference)
#include <cuda_runtime.h>
#include <math.h>

#define MM 4096
#define DD 2048
#define INV_SQRT_M 0.015625f   // 1/sqrt(4096) exact

// ---------------- device scratch ----------------
__device__ float g_qt[MM];
__device__ float g_k[MM];
__device__ float g_v[MM];
__device__ float g_it, g_ft, g_ot;
__device__ float g_kqt, g_denom;

// ---------------- kernel 1: fused q/k/v matvecs + gates ----------------
// Round-2 geometry (best measured): grid = MM+1 blocks, 256 threads,
// one row-triple (Wq/Wk/Wv row b) per block, MLP=6.
// KEY CHANGE: weights are loaded with DEFAULT cache policy (no __ldcs) so
// the 96MB of weights can stay resident in the ~126MB L2 across graph
// replays; the cp kernel uses evict-first streaming so it won't evict them.
__global__ __launch_bounds__(256) void mv_kernel(
    const float* __restrict__ x,
    const float* __restrict__ Wq, const float* __restrict__ bq,
    const float* __restrict__ Wk, const float* __restrict__ bk,
    const float* __restrict__ Wv, const float* __restrict__ bV,
    const float* __restrict__ Wi, const float* __restrict__ bi,
    const float* __restrict__ Wf, const float* __restrict__ bf,
    const float* __restrict__ Wo, const float* __restrict__ bo)
{
    const int b = blockIdx.x;
    const int t = threadIdx.x;

    const float *rA, *rB, *rC;
    const bool gate = (b == MM);
    if (!gate) {
        rA = Wq + (size_t)b * DD;
        rB = Wk + (size_t)b * DD;
        rC = Wv + (size_t)b * DD;
    } else {
        rA = Wi; rB = Wf; rC = Wo;
    }

    const float4* A4 = reinterpret_cast<const float4*>(rA);
    const float4* B4 = reinterpret_cast<const float4*>(rB);
    const float4* C4 = reinterpret_cast<const float4*>(rC);
    const float4* x4 = reinterpret_cast<const float4*>(x);

    // 6 independent loads, front-batched (MLP=6), default cache policy
    float4 a0 = A4[t];
    float4 a1 = A4[t + 256];
    float4 k0 = B4[t];
    float4 k1 = B4[t + 256];
    float4 v0 = C4[t];
    float4 v1 = C4[t + 256];
    float4 x0 = x4[t];
    float4 x1 = x4[t + 256];

    float sa = a0.x * x0.x + a0.y * x0.y + a0.z * x0.z + a0.w * x0.w
             + a1.x * x1.x + a1.y * x1.y + a1.z * x1.z + a1.w * x1.w;
    float sk = k0.x * x0.x + k0.y * x0.y + k0.z * x0.z + k0.w * x0.w
             + k1.x * x1.x + k1.y * x1.y + k1.z * x1.z + k1.w * x1.w;
    float sv = v0.x * x0.x + v0.y * x0.y + v0.z * x0.z + v0.w * x0.w
             + v1.x * x1.x + v1.y * x1.y + v1.z * x1.z + v1.w * x1.w;

    #pragma unroll
    for (int o = 16; o > 0; o >>= 1) {
        sa += __shfl_down_sync(0xFFFFFFFFu, sa, o);
        sk += __shfl_down_sync(0xFFFFFFFFu, sk, o);
        sv += __shfl_down_sync(0xFFFFFFFFu, sv, o);
    }

    __shared__ float wsa[8], wsk[8], wsv[8];
    if ((t & 31) == 0) {
        int w = t >> 5;
        wsa[w] = sa; wsk[w] = sk; wsv[w] = sv;
    }
    __syncthreads();
    if (t < 8) {
        float ra = wsa[t], rk = wsk[t], rv = wsv[t];
        #pragma unroll
        for (int o = 4; o > 0; o >>= 1) {
            ra += __shfl_down_sync(0xFFu, ra, o, 8);
            rk += __shfl_down_sync(0xFFu, rk, o, 8);
            rv += __shfl_down_sync(0xFFu, rv, o, 8);
        }
        if (t == 0) {
            if (!gate) {
                g_qt[b] = ra + bq[b];
                g_k[b]  = INV_SQRT_M * (rk + bk[b]);
                g_v[b]  = rv + bV[b];
            } else {
                g_it = expf(ra + bi[0]);
                g_ft = expf(rk + bf[0]);
                float z = rv + bo[0];
                g_ot = 1.0f / (1.0f + expf(-z));
            }
        }
    }
}

// ---------------- kernel 2: n-update + tiny reductions ----------------
// n_i = ft*n_prev_i + it*k_i ; kqt = k·qt ; denom = max(|n·qt|, 1)
__global__ __launch_bounds__(1024) void nred_kernel(
    const float* __restrict__ n_prev, float* __restrict__ out_n)
{
    const int t = threadIdx.x;
    const float ft = g_ft, it = g_it;
    float kqt = 0.f, nqt = 0.f;
    #pragma unroll
    for (int u = 0; u < MM / 1024; u++) {
        int i = t + u * 1024;
        float k = g_k[i];
        float q = g_qt[i];
        kqt += k * q;
        float n = ft * n_prev[i] + it * k;
        out_n[i] = n;
        nqt += n * q;
    }
    #pragma unroll
    for (int o = 16; o > 0; o >>= 1) {
        kqt += __shfl_down_sync(0xFFFFFFFFu, kqt, o);
        nqt += __shfl_down_sync(0xFFFFFFFFu, nqt, o);
    }
    __shared__ float sk[32], sn[32];
    if ((t & 31) == 0) { sk[t >> 5] = kqt; sn[t >> 5] = nqt; }
    __syncthreads();
    if (t < 32) {
        float a = sk[t], b = sn[t];
        #pragma unroll
        for (int o = 16; o > 0; o >>= 1) {
            a += __shfl_down_sync(0xFFFFFFFFu, a, o);
            b += __shfl_down_sync(0xFFFFFFFFu, b, o);
        }
        if (t == 0) {
            g_kqt = a;
            g_denom = fmaxf(fabsf(b), 1.0f);
        }
    }
}

// ---------------- kernel 3: cp stream -> C write + cp@qt + ht ----------------
// Round-2 geometry: 2 rows per 512-thread block, 4 front-batched streaming
// loads per thread. cp/C use evict-first streaming (__ldcs/__stcs) so they
// do not evict the L2-resident weights.
__global__ __launch_bounds__(512) void cp_kernel(
    const float* __restrict__ cp, float* __restrict__ outC,
    float* __restrict__ outH)
{
    const int i0 = blockIdx.x * 2;
    const int i1 = i0 + 1;
    const int t  = threadIdx.x;
    const float ft   = g_ft;
    const float it   = g_it;
    const float itv0 = it * g_v[i0];
    const float itv1 = it * g_v[i1];

    const float4* cpA = reinterpret_cast<const float4*>(cp   + (size_t)i0 * MM);
    const float4* cpB = reinterpret_cast<const float4*>(cp   + (size_t)i1 * MM);
    float4*       CA  = reinterpret_cast<float4*>(outC + (size_t)i0 * MM);
    float4*       CB  = reinterpret_cast<float4*>(outC + (size_t)i1 * MM);
    const float4* k4  = reinterpret_cast<const float4*>(g_k);
    const float4* q4  = reinterpret_cast<const float4*>(g_qt);

    const int j0 = t;
    const int j1 = t + 512;

    // 4 independent streaming loads front-batched (MLP=4)
    float4 c00 = __ldcs(&cpA[j0]);
    float4 c01 = __ldcs(&cpA[j1]);
    float4 c10 = __ldcs(&cpB[j0]);
    float4 c11 = __ldcs(&cpB[j1]);
    float4 ka = k4[j0], kb = k4[j1];
    float4 qa = q4[j0], qb = q4[j1];

    float4 o;
    o.x = ft * c00.x + itv0 * ka.x; o.y = ft * c00.y + itv0 * ka.y;
    o.z = ft * c00.z + itv0 * ka.z; o.w = ft * c00.w + itv0 * ka.w;
    __stcs(&CA[j0], o);
    o.x = ft * c01.x + itv0 * kb.x; o.y = ft * c01.y + itv0 * kb.y;
    o.z = ft * c01.z + itv0 * kb.z; o.w = ft * c01.w + itv0 * kb.w;
    __stcs(&CA[j1], o);
    o.x = ft * c10.x + itv1 * ka.x; o.y = ft * c10.y + itv1 * ka.y;
    o.z = ft * c10.z + itv1 * ka.z; o.w = ft * c10.w + itv1 * ka.w;
    __stcs(&CB[j0], o);
    o.x = ft * c11.x + itv1 * kb.x; o.y = ft * c11.y + itv1 * kb.y;
    o.z = ft * c11.z + itv1 * kb.z; o.w = ft * c11.w + itv1 * kb.w;
    __stcs(&CB[j1], o);

    float s0 = c00.x * qa.x + c00.y * qa.y + c00.z * qa.z + c00.w * qa.w
             + c01.x * qb.x + c01.y * qb.y + c01.z * qb.z + c01.w * qb.w;
    float s1 = c10.x * qa.x + c10.y * qa.y + c10.z * qa.z + c10.w * qa.w
             + c11.x * qb.x + c11.y * qb.y + c11.z * qb.z + c11.w * qb.w;

    #pragma unroll
    for (int o2 = 16; o2 > 0; o2 >>= 1) {
        s0 += __shfl_down_sync(0xFFFFFFFFu, s0, o2);
        s1 += __shfl_down_sync(0xFFFFFFFFu, s1, o2);
    }
    __shared__ float ws0[16], ws1[16];
    if ((t & 31) == 0) { ws0[t >> 5] = s0; ws1[t >> 5] = s1; }
    __syncthreads();
    if (t < 16) {
        float a = ws0[t], b = ws1[t];
        #pragma unroll
        for (int o2 = 8; o2 > 0; o2 >>= 1) {
            a += __shfl_down_sync(0xFFFFu, a, o2, 16);
            b += __shfl_down_sync(0xFFFFu, b, o2, 16);
        }
        if (t == 0) {
            const float inv = g_ot / g_denom;
            const float kqt = g_kqt;
            outH[i0] = inv * (ft * a + itv0 * kqt);
            outH[i1] = inv * (ft * b + itv1 * kqt);
        }
    }
}

// ---------------- launch ----------------
extern "C" void kernel_launch(void* const* d_in, const int* in_sizes, int n_in,
                              void* d_out, int out_size)
{
    const float* x      = (const float*)d_in[0];
    const float* cp     = (const float*)d_in[1];
    const float* n_prev = (const float*)d_in[2];
    const float* Wq     = (const float*)d_in[3];
    const float* bq     = (const float*)d_in[4];
    const float* Wk     = (const float*)d_in[5];
    const float* bk     = (const float*)d_in[6];
    const float* Wv     = (const float*)d_in[7];
    const float* bV     = (const float*)d_in[8];
    const float* Wi     = (const float*)d_in[9];
    const float* bi     = (const float*)d_in[10];
    const float* Wf     = (const float*)d_in[11];
    const float* bf     = (const float*)d_in[12];
    const float* Wo     = (const float*)d_in[13];
    const float* bo     = (const float*)d_in[14];

    float* out  = (float*)d_out;
    float* outH = out;                        // ht: M
    float* outC = out + MM;                   // C : M*M
    float* outN = out + MM + (size_t)MM * MM; // n : M

    mv_kernel<<<MM + 1, 256>>>(x, Wq, bq, Wk, bk, Wv, bV,
                               Wi, bi, Wf, bf, Wo, bo);
    nred_kernel<<<1, 1024>>>(n_prev, outN);
    cp_kernel<<<MM / 2, 512>>>(cp, outC, outH);
}